// round 7
// baseline (speedup 1.0000x reference)
#include <cuda_runtime.h>
#include <cuda_bf16.h>

// Problem constants (fixed by the dataset)
#define BB   64
#define MM   64   // ctrl rows (u direction)
#define NN   64   // ctrl cols (v direction)
#define OUT  512  // output grid per dim

#define U_TILE      32
#define THREADS     128
#define V_PER_BLOCK 256   // 2 v per thread

typedef unsigned long long ull;

// ---- packed f32x2 helpers (sm_103a FFMA2 path; see SASS_QUICKREF) ----
__device__ __forceinline__ ull pack2(float lo, float hi) {
    ull r; asm("mov.b64 %0, {%1, %2};" : "=l"(r) : "f"(lo), "f"(hi)); return r;
}
__device__ __forceinline__ float2 unpack2(ull p) {
    float2 v; asm("mov.b64 {%0, %1}, %2;" : "=f"(v.x), "=f"(v.y) : "l"(p)); return v;
}
__device__ __forceinline__ ull fma2(ull a, ull b, ull c) {
    ull d; asm("fma.rn.f32x2 %0, %1, %2, %3;" : "=l"(d) : "l"(a), "l"(b), "l"(c)); return d;
}
__device__ __forceinline__ ull mul2(ull a, ull b) {
    ull d; asm("mul.rn.f32x2 %0, %1, %2;" : "=l"(d) : "l"(a), "l"(b)); return d;
}

// ctrl float4 (x,y,z,w) reinterpreted as ulonglong2: .x = (x,y) pack, .y = (z,w) pack
__global__ __launch_bounds__(THREADS) void surfeval_kernel(
    const ulonglong2* __restrict__ ctrl2,  // (B, M, N)
    const float4* __restrict__ Nu4,        // (OUT)
    const float4* __restrict__ Nv4,        // (OUT)
    const int* __restrict__ iu,            // (OUT,4) int32
    const int* __restrict__ iv,            // (OUT,4) int32
    float* __restrict__ out)               // (B, OUT, OUT, 3)
{
    __shared__ ull s_Nu[U_TILE][4];   // per-u splatted (nu.l, nu.l) pairs
    __shared__ int s_row0[U_TILE];

    const int tid = threadIdx.x;
    const int vt  = blockIdx.x;
    const int ut  = blockIdx.y;
    const int b   = blockIdx.z;

    const int u_lo = ut * U_TILE;
    const int u_hi = u_lo + U_TILE;

    if (tid < U_TILE) {
        const float4 nu = __ldg(&Nu4[u_lo + tid]);
        s_Nu[tid][0] = pack2(nu.x, nu.x);
        s_Nu[tid][1] = pack2(nu.y, nu.y);
        s_Nu[tid][2] = pack2(nu.z, nu.z);
        s_Nu[tid][3] = pack2(nu.w, nu.w);
        s_row0[tid]  = __ldg(&iu[(u_lo + tid) * 4]);
    }
    __syncthreads();

    const int v0 = vt * V_PER_BLOCK + 2 * tid;   // this thread: v0, v0+1
    const float4 nva = __ldg(&Nv4[v0]);
    const float4 nvb = __ldg(&Nv4[v0 + 1]);
    const int iva = __ldg(&iv[v0 * 4]);
    const int ivb = __ldg(&iv[(v0 + 1) * 4]);

    const ull na0 = pack2(nva.x, nva.x), na1 = pack2(nva.y, nva.y);
    const ull na2 = pack2(nva.z, nva.z), na3 = pack2(nva.w, nva.w);
    const ull nb0 = pack2(nvb.x, nvb.x), nb1 = pack2(nvb.y, nvb.y);
    const ull nb2 = pack2(nvb.z, nvb.z), nb3 = pack2(nvb.w, nvb.w);

    const ulonglong2* ca  = ctrl2 + (size_t)b * MM * NN + iva;
    const ulonglong2* cbp = ctrl2 + (size_t)b * MM * NN + ivb;

    float* op = out + (((size_t)b * OUT + u_lo) * OUT + v0) * 3;
    const size_t ustride = (size_t)OUT * 3;

    int u = u_lo;
    #pragma unroll 1
    while (u < u_hi) {
        const int row0 = s_row0[u - u_lo];

        // rowdots for both v, packed (xy)/(zw), halved FMA count via f32x2
        ull rdaxy[4], rdazw[4], rdbxy[4], rdbzw[4];
        {
            const ulonglong2* pa = ca  + (size_t)row0 * NN;
            const ulonglong2* pb = cbp + (size_t)row0 * NN;
            #pragma unroll
            for (int l = 0; l < 4; ++l) {
                ulonglong2 c0 = pa[0], c1 = pa[1], c2 = pa[2], c3 = pa[3];
                rdaxy[l] = fma2(na3, c3.x, fma2(na2, c2.x, fma2(na1, c1.x, mul2(na0, c0.x))));
                rdazw[l] = fma2(na3, c3.y, fma2(na2, c2.y, fma2(na1, c1.y, mul2(na0, c0.y))));
                c0 = pb[0]; c1 = pb[1]; c2 = pb[2]; c3 = pb[3];
                rdbxy[l] = fma2(nb3, c3.x, fma2(nb2, c2.x, fma2(nb1, c1.x, mul2(nb0, c0.x))));
                rdbzw[l] = fma2(nb3, c3.y, fma2(nb2, c2.y, fma2(nb1, c1.y, mul2(nb0, c0.y))));
                pa += NN; pb += NN;
            }
        }

        // sweep all u sharing this span
        #pragma unroll 1
        do {
            const int uo = u - u_lo;
            const ull nx = s_Nu[uo][0], ny = s_Nu[uo][1];
            const ull nz = s_Nu[uo][2], nw = s_Nu[uo][3];

            const ull axy = fma2(nw, rdaxy[3], fma2(nz, rdaxy[2], fma2(ny, rdaxy[1], mul2(nx, rdaxy[0]))));
            const ull azw = fma2(nw, rdazw[3], fma2(nz, rdazw[2], fma2(ny, rdazw[1], mul2(nx, rdazw[0]))));
            const ull bxy = fma2(nw, rdbxy[3], fma2(nz, rdbxy[2], fma2(ny, rdbxy[1], mul2(nx, rdbxy[0]))));
            const ull bzw = fma2(nw, rdbzw[3], fma2(nz, rdbzw[2], fma2(ny, rdbzw[1], mul2(nx, rdbzw[0]))));

            const float2 zw0 = unpack2(azw);
            const float2 zw1 = unpack2(bzw);
            const float i0 = __fdividef(1.0f, zw0.y);
            const float i1 = __fdividef(1.0f, zw1.y);

            const ull  sxy0 = mul2(axy, pack2(i0, i0));   // (x0/w0, y0/w0)
            const ull  sxy1 = mul2(bxy, pack2(i1, i1));   // (x1/w1, y1/w1)
            const float z0  = zw0.x * i0;
            const float z1  = zw1.x * i1;
            const float2 s1 = unpack2(sxy1);

            // 24 contiguous bytes per lane (v0,v0+1), 8B aligned -> 3x STG.64
            ull* o64 = (ull*)op;
            o64[0] = sxy0;            // x0 y0
            o64[1] = pack2(z0, s1.x); // z0 x1
            o64[2] = pack2(s1.y, z1); // y1 z1

            op += ustride;
            ++u;
        } while (u < u_hi && s_row0[u - u_lo] == row0);
    }
}

extern "C" void kernel_launch(void* const* d_in, const int* in_sizes, int n_in,
                              void* d_out, int out_size) {
    const ulonglong2* ctrl = (const ulonglong2*)d_in[0];
    const float4*     Nu   = (const float4*)d_in[1];
    const float4*     Nv   = (const float4*)d_in[2];
    const int*        iu   = (const int*)d_in[3];
    const int*        iv   = (const int*)d_in[4];
    float*            out  = (float*)d_out;

    dim3 grid(OUT / V_PER_BLOCK, OUT / U_TILE, BB);   // (2, 16, 64) = 2048 CTAs
    surfeval_kernel<<<grid, THREADS>>>(ctrl, Nu, Nv, iu, iv, out);
}